// round 16
// baseline (speedup 1.0000x reference)
#include <cuda_runtime.h>
#include <cuda_fp16.h>

typedef unsigned int u32;
#define DEVINL __device__ __forceinline__

static constexpr int Bb = 8, Ll = 2048, Dd = 64;
static constexpr int TQ = 128, NT = 256, NTILES = 16;
static constexpr int NSTAGE = 4;
static constexpr float QSCALE = 0.18033688011112042f; // log2(e)/8

// scratch: per tile one contiguous blob: K(16KB swz) | km*V(16KB swz) | kmcol(2KB) pad to 36KB
static constexpr int OF_K = 0;
static constexpr int OF_V = 16384;
static constexpr int OF_M = 32768;
static constexpr int TILEB = 36864;
__device__ __align__(16) unsigned char g_kv[Bb][16][TILEB];
__device__ __align__(16) unsigned char g_q[Bb][16][16384];

// smem layout
static constexpr int STAGESZ = TILEB;          // 4 stages: 0..147455
static constexpr int SM_Q   = 147456;          // fp16 [128][64] = 16KB
static constexpr int SM_BAR = 163840;          // full[4] @ +0, empty[4] @ +32
static constexpr int SM_TOT = 163968;

DEVINL u32 smem_u32(const void* p) {
    u32 a;
    asm("{ .reg .u64 t; cvta.to.shared.u64 t, %1; cvt.u32.u64 %0, t; }" : "=r"(a) : "l"(p));
    return a;
}
DEVINL u32 swz(u32 o) { return o ^ ((o >> 3) & 0x70); }
DEVINL float ex2f(float x) { float r; asm("ex2.approx.f32 %0, %1;" : "=f"(r) : "f"(x)); return r; }
DEVINL u32 packh2(float lo, float hi) {
    u32 r; asm("cvt.rn.f16x2.f32 %0, %1, %2;" : "=r"(r) : "f"(hi), "f"(lo)); return r;
}

DEVINL void ldsm4(u32* r, u32 a) {
    asm volatile("ldmatrix.sync.aligned.m8n8.x4.shared.b16 {%0,%1,%2,%3}, [%4];"
                 : "=r"(r[0]), "=r"(r[1]), "=r"(r[2]), "=r"(r[3]) : "r"(a) : "memory");
}
DEVINL void ldsm4t(u32* r, u32 a) {
    asm volatile("ldmatrix.sync.aligned.m8n8.x4.trans.shared.b16 {%0,%1,%2,%3}, [%4];"
                 : "=r"(r[0]), "=r"(r[1]), "=r"(r[2]), "=r"(r[3]) : "r"(a) : "memory");
}
DEVINL void ldsm2t(u32* r, u32 a) {
    asm volatile("ldmatrix.sync.aligned.m8n8.x2.trans.shared.b16 {%0,%1}, [%2];"
                 : "=r"(r[0]), "=r"(r[1]) : "r"(a) : "memory");
}
DEVINL void mma16816(float* c, const u32* a, u32 b0, u32 b1) {
    asm("mma.sync.aligned.m16n8k16.row.col.f32.f16.f16.f32 "
        "{%0,%1,%2,%3}, {%4,%5,%6,%7}, {%8,%9}, {%0,%1,%2,%3};"
        : "+f"(c[0]), "+f"(c[1]), "+f"(c[2]), "+f"(c[3])
        : "r"(a[0]), "r"(a[1]), "r"(a[2]), "r"(a[3]), "r"(b0), "r"(b1));
}

DEVINL void cpa16(u32 dst, const void* src) {
    asm volatile("cp.async.cg.shared.global [%0], [%1], 16;" :: "r"(dst), "l"(src) : "memory");
}
DEVINL void cpa_commit() { asm volatile("cp.async.commit_group;" ::: "memory"); }
DEVINL void cpa_wait0()  { asm volatile("cp.async.wait_group 0;" ::: "memory"); }

DEVINL void mbar_init(u32 bar, u32 cnt) {
    asm volatile("mbarrier.init.shared.b64 [%0], %1;" :: "r"(bar), "r"(cnt) : "memory");
}
DEVINL void mbar_arrive(u32 bar) {
    asm volatile("mbarrier.arrive.shared.b64 _, [%0];" :: "r"(bar) : "memory");
}
DEVINL void mbar_expect_tx(u32 bar, u32 bytes) {
    asm volatile("mbarrier.arrive.expect_tx.shared.b64 _, [%0], %1;"
                 :: "r"(bar), "r"(bytes) : "memory");
}
DEVINL void mbar_wait(u32 bar, u32 parity) {
    asm volatile(
        "{\n\t.reg .pred P;\n\t"
        "WL_%=:\n\t"
        "mbarrier.try_wait.parity.acquire.cta.shared::cta.b64 P, [%0], %1, 0x989680;\n\t"
        "@P bra WD_%=;\n\t"
        "bra WL_%=;\n\t"
        "WD_%=:\n\t}"
        :: "r"(bar), "r"(parity) : "memory");
}
DEVINL void bulk_cp(u32 dst, const void* src, u32 bytes, u32 bar) {
    asm volatile(
        "cp.async.bulk.shared::cta.global.mbarrier::complete_tx::bytes [%0], [%1], %2, [%3];"
        :: "r"(dst), "l"(src), "r"(bytes), "r"(bar) : "memory");
}

// ---------------- kernel 1: fp32 -> fp16, tile-swizzled; V masked; km column ----------------
__global__ void __launch_bounds__(256, 4)
presplit(const float* __restrict__ Q, const float* __restrict__ K,
         const float* __restrict__ V, const float* __restrict__ KM)
{
    int tensor = blockIdx.y;                       // 0=K, 1=V(masked)+kmcol, 2=Q(scaled)
    int c = blockIdx.x * 256 + threadIdx.x;
    int b  = c >> 14;
    int l  = (c >> 3) & 2047;
    int d0 = (c & 7) * 8;

    const float* src = (tensor == 0 ? K : tensor == 1 ? V : Q)
                       + ((size_t)(b * Ll + l) * Dd + d0);
    float4 a = *reinterpret_cast<const float4*>(src);
    float4 e = *reinterpret_cast<const float4*>(src + 4);
    float scl = (tensor == 2) ? QSCALE : 1.0f;
    float km = 0.f;
    if (tensor == 1) { km = KM[b * Ll + l]; scl = km; }
    if (tensor != 0) {
        a.x *= scl; a.y *= scl; a.z *= scl; a.w *= scl;
        e.x *= scl; e.y *= scl; e.z *= scl; e.w *= scl;
    }
    uint4 H = make_uint4(packh2(a.x, a.y), packh2(a.z, a.w),
                         packh2(e.x, e.y), packh2(e.z, e.w));
    int tile = l >> 7, row = l & 127;
    u32 off = swz((u32)(row * 128 + d0 * 2));
    unsigned char* dstp;
    if (tensor == 2)      dstp = g_q[b][tile];
    else if (tensor == 0) dstp = g_kv[b][tile] + OF_K;
    else                  dstp = g_kv[b][tile] + OF_V;
    *reinterpret_cast<uint4*>(dstp + off) = H;
    if (tensor == 1 && d0 == 0) {
        // km column tile: [128 rows][8 half cols], col0 = km, rest 0
        *reinterpret_cast<uint4*>(g_kv[b][tile] + OF_M + row * 16) =
            make_uint4(packh2(km, 0.f), 0u, 0u, 0u);
    }
}

// ---------------- kernel 2: attention; Q resident, cross-chunk software pipeline ----------------
__global__ void __launch_bounds__(NT, 1)
attn_mma(const float* __restrict__ QM, float* __restrict__ Out)
{
    extern __shared__ char sm[];
    const u32 smb = smem_u32(sm);
    const int tid = threadIdx.x, w = tid >> 5, L = tid & 31;
    const int b = blockIdx.y, qt = blockIdx.x, q0 = qt * TQ;
    const int mg = w >> 1, kh = w & 1;   // 4 row-groups x 2 key-halves

    // init: Q (16KB) via cp.async; barriers
    {
#pragma unroll
        for (int r = 0; r < 4; ++r) {
            u32 o = (u32)tid * 16 + (u32)r * 4096;
            cpa16(smb + SM_Q + o, g_q[b][qt] + o);
        }
        cpa_commit();
        if (tid == 0) {
#pragma unroll
            for (int s = 0; s < NSTAGE; ++s) {
                mbar_init(smb + SM_BAR + s * 8, 1);        // full
                mbar_init(smb + SM_BAR + 32 + s * 8, 8);   // empty: 8 warps
            }
        }
        cpa_wait0();
        __syncthreads();
    }

    // producer prologue: stages 0..2
    if (tid == 0) {
#pragma unroll
        for (int it = 0; it < 3; ++it) {
            u32 s = (u32)it & 3;
            u32 fb = smb + SM_BAR + s * 8;
            mbar_wait(smb + SM_BAR + 32 + s * 8, 1u);
            mbar_expect_tx(fb, (u32)TILEB);
            bulk_cp(smb + s * STAGESZ, g_kv[b][it], (u32)TILEB, fb);
        }
    }

    // lane addressing
    const int m = L >> 3;
    const u32 xm = (u32)(L & 7) << 4;
    const int arw = (m & 1) * 8 + (L & 7);

    // Q fragments: register-resident (2 m-tiles x 4 k-chunks)
    u32 qf[2][4][4];
#pragma unroll
    for (int mt = 0; mt < 2; ++mt)
#pragma unroll
        for (int kc = 0; kc < 4; ++kc)
            ldsm4(qf[mt][kc],
                  smb + SM_Q + (u32)(mg * 32 + mt * 16 + arw) * 128
                  + (((u32)kc * 32 + (u32)(m >> 1) * 16) ^ xm));

    u32 koff[4], voff[4];
#pragma unroll
    for (int i = 0; i < 4; ++i) {
        koff[i] = OF_K + (u32)kh * 8192 + (u32)((m >> 1) * 8 + (L & 7)) * 128
                + (((u32)i * 32 + (u32)(m & 1) * 16) ^ xm);
        voff[i] = OF_V + (u32)kh * 8192 + (u32)arw * 128
                + (((u32)i * 32 + (u32)(m >> 1) * 16) ^ xm);
    }
    const u32 moff0 = OF_M + (u32)kh * 1024 + (u32)arw * 16;

    float oacc[2][8][4];
    float oaccE[2][4];   // extra n8 tile: col 64 = rowsum
#pragma unroll
    for (int mt = 0; mt < 2; ++mt) {
#pragma unroll
        for (int j = 0; j < 8; ++j)
            { oacc[mt][j][0] = 0; oacc[mt][j][1] = 0; oacc[mt][j][2] = 0; oacc[mt][j][3] = 0; }
        oaccE[mt][0] = 0; oaccE[mt][1] = 0; oaccE[mt][2] = 0; oaccE[mt][3] = 0;
    }

    for (int kt = 0; kt < NTILES; ++kt) {
        const u32 s = (u32)kt & 3;
        const u32 sbase = smb + s * STAGESZ;
        mbar_wait(smb + SM_BAR + s * 8, ((u32)kt >> 2) & 1u);

        // G1 for a 16-key chunk
        auto g1 = [&](float (*sc)[2][4], u32 coff) {
#pragma unroll
            for (int mt = 0; mt < 2; ++mt)
#pragma unroll
                for (int j = 0; j < 2; ++j)
                    { sc[mt][j][0] = 0; sc[mt][j][1] = 0; sc[mt][j][2] = 0; sc[mt][j][3] = 0; }
#pragma unroll
            for (int kc = 0; kc < 4; ++kc) {
                u32 bh[4];
                ldsm4(bh, sbase + koff[kc] + coff);
                mma16816(sc[0][0], qf[0][kc], bh[0], bh[1]);
                mma16816(sc[0][1], qf[0][kc], bh[2], bh[3]);
                mma16816(sc[1][0], qf[1][kc], bh[0], bh[1]);
                mma16816(sc[1][1], qf[1][kc], bh[2], bh[3]);
            }
        };

        // software pipeline: G1(c+1) issued before exp/G2 of chunk c
        float sacc[2][2][2][4];    // [buf][mt][j][4]
        g1(sacc[0], 0);
#pragma unroll
        for (int c = 0; c < 4; ++c) {
            const int cur = c & 1, nxt = cur ^ 1;
            const u32 coff = (u32)c * 2048;
            if (c < 3) g1(sacc[nxt], coff + 2048);

            // V fragments early (independent of exp)
            u32 vh[4][4];
#pragma unroll
            for (int j2 = 0; j2 < 4; ++j2)
                ldsm4t(vh[j2], sbase + voff[j2] + coff);
            u32 bm[2];
            ldsm2t(bm, sbase + moff0 + (u32)c * 256);

            // exp -> A fragments
            u32 Ah[2][4];
#pragma unroll
            for (int mt = 0; mt < 2; ++mt)
#pragma unroll
                for (int j = 0; j < 2; ++j) {
                    float p0 = ex2f(sacc[cur][mt][j][0]);
                    float p1 = ex2f(sacc[cur][mt][j][1]);
                    float p2 = ex2f(sacc[cur][mt][j][2]);
                    float p3 = ex2f(sacc[cur][mt][j][3]);
                    Ah[mt][2 * j]     = packh2(p0, p1);
                    Ah[mt][2 * j + 1] = packh2(p2, p3);
                }

            // rowsum via km-column MMA
            mma16816(oaccE[0], Ah[0], bm[0], bm[1]);
            mma16816(oaccE[1], Ah[1], bm[0], bm[1]);

            // G2 chunk c
#pragma unroll
            for (int j2 = 0; j2 < 4; ++j2) {
                mma16816(oacc[0][2 * j2],     Ah[0], vh[j2][0], vh[j2][1]);
                mma16816(oacc[0][2 * j2 + 1], Ah[0], vh[j2][2], vh[j2][3]);
                mma16816(oacc[1][2 * j2],     Ah[1], vh[j2][0], vh[j2][1]);
                mma16816(oacc[1][2 * j2 + 1], Ah[1], vh[j2][2], vh[j2][3]);
            }
        }

        if (L == 0) mbar_arrive(smb + SM_BAR + 32 + s * 8);

        if (tid == 0 && kt + 3 < NTILES) {
            const int it = kt + 3;
            u32 s2 = (u32)it & 3;
            u32 fb = smb + SM_BAR + s2 * 8;
            mbar_wait(smb + SM_BAR + 32 + s2 * 8, ((((u32)it >> 2) & 1u) ^ 1u));
            mbar_expect_tx(fb, (u32)TILEB);
            bulk_cp(smb + s2 * STAGESZ, g_kv[b][it], (u32)TILEB, fb);
        }
    }

    // ---- epilogue: rowsum from extra tile, 2-way key-half combine ----
    float rsA[2], rsB[2];
#pragma unroll
    for (int mt = 0; mt < 2; ++mt) {
        rsA[mt] = __shfl_sync(0xFFFFFFFFu, oaccE[mt][0], L & ~3);
        rsB[mt] = __shfl_sync(0xFFFFFFFFu, oaccE[mt][2], L & ~3);
    }
    __syncthreads();   // pipeline drained; stage smem reusable

    float* OS = reinterpret_cast<float*>(sm);            // [128][64] f32 = 32KB
    float* RS = reinterpret_cast<float*>(sm + 32768);    // [128]
    if (kh == 1) {
#pragma unroll
        for (int mt = 0; mt < 2; ++mt) {
            int ra = mg * 32 + mt * 16 + (L >> 2);
            int rb = ra + 8;
#pragma unroll
            for (int j = 0; j < 8; ++j) {
                *reinterpret_cast<float2*>(&OS[ra * 64 + 8 * j + 2 * (L & 3)]) =
                    make_float2(oacc[mt][j][0], oacc[mt][j][1]);
                *reinterpret_cast<float2*>(&OS[rb * 64 + 8 * j + 2 * (L & 3)]) =
                    make_float2(oacc[mt][j][2], oacc[mt][j][3]);
            }
            if ((L & 3) == 0) { RS[ra] = rsA[mt]; RS[rb] = rsB[mt]; }
        }
    }
    __syncthreads();
    if (kh == 0) {
#pragma unroll
        for (int mt = 0; mt < 2; ++mt) {
            int ra = mg * 32 + mt * 16 + (L >> 2);
            int rb = ra + 8;
            float sa = rsA[mt] + RS[ra];
            float sb = rsB[mt] + RS[rb];
            float dva = QM[b * Ll + q0 + ra] / fmaxf(sa, 2e-15f);
            float dvb = QM[b * Ll + q0 + rb] / fmaxf(sb, 2e-15f);
            float* oa = Out + (size_t)(b * Ll + q0 + ra) * Dd + 2 * (L & 3);
            float* ob = Out + (size_t)(b * Ll + q0 + rb) * Dd + 2 * (L & 3);
#pragma unroll
            for (int j = 0; j < 8; ++j) {
                int ca = ra * 64 + 8 * j + 2 * (L & 3);
                int cb = rb * 64 + 8 * j + 2 * (L & 3);
                float2 ua = *reinterpret_cast<const float2*>(&OS[ca]);
                float2 ub = *reinterpret_cast<const float2*>(&OS[cb]);
                *reinterpret_cast<float2*>(oa + 8 * j) =
                    make_float2((oacc[mt][j][0] + ua.x) * dva,
                                (oacc[mt][j][1] + ua.y) * dva);
                *reinterpret_cast<float2*>(ob + 8 * j) =
                    make_float2((oacc[mt][j][2] + ub.x) * dvb,
                                (oacc[mt][j][3] + ub.y) * dvb);
            }
        }
    }
}

extern "C" void kernel_launch(void* const* d_in, const int* in_sizes, int n_in,
                              void* d_out, int out_size) {
    const float* Q  = (const float*)d_in[0];
    const float* K  = (const float*)d_in[1];
    const float* V  = (const float*)d_in[2];
    const float* QM = (const float*)d_in[3];
    const float* KM = (const float*)d_in[4];
    float* Out = (float*)d_out;

    presplit<<<dim3(512, 3), 256>>>(Q, K, V, KM);

    cudaFuncSetAttribute(attn_mma, cudaFuncAttributeMaxDynamicSharedMemorySize, SM_TOT);
    dim3 grid(Ll / TQ, Bb);   // 16 q-tiles x 8 batches = 128 CTAs, 1 per SM
    attn_mma<<<grid, NT, SM_TOT>>>(QM, Out);
}